// round 14
// baseline (speedup 1.0000x reference)
#include <cuda_runtime.h>
#include <cuda_bf16.h>
#include <cuda_fp16.h>
#include <math.h>
#include <stdint.h>

#define BB 2
#define LL 2048
#define DD 1024
#define HH 16
#define HDIM 64
#define MROWS (BB*LL)   // 4096

// Scratch (allocation-free per harness rules)
static __device__ float g_Q[MROWS * DD];
static __device__ float g_K[MROWS * DD];
static __device__ float g_V[MROWS * DD];
static __device__ float g_A[MROWS * DD];
static __device__ int   g_kpm[BB * LL];

// ---------------------------------------------------------------------------
// Normalize key_padding_mask regardless of on-disk dtype (validated R9-R12).
// ---------------------------------------------------------------------------
__global__ void normalize_kpm(const int* __restrict__ raw)
{
    __shared__ int ok_int, ok_float;
    int tid = threadIdx.x;
    if (tid == 0) { ok_int = 1; ok_float = 1; }
    __syncthreads();
    for (int i = tid; i < BB * LL; i += blockDim.x) {
        int v = raw[i];
        if (v != 0 && v != 1)          ok_int = 0;
        if (v != 0 && v != 0x3F800000) ok_float = 0;
    }
    __syncthreads();
    const unsigned char* raw8 = (const unsigned char*)raw;
    for (int i = tid; i < BB * LL; i += blockDim.x) {
        int out;
        if (ok_int)        out = raw[i];
        else if (ok_float) out = raw[i] ? 1 : 0;
        else               out = raw8[i] ? 1 : 0;
        g_kpm[i] = out;
    }
}

// ---------------------------------------------------------------------------
// fp16 split helpers: x = hi + lo, both fp16 (11-bit mantissa each;
// residual structure ~2^-22 per product, like tf32x3).
// ---------------------------------------------------------------------------
__device__ __forceinline__ void f16split2(float x, float y, uint32_t& hi, uint32_t& lo)
{
    __half hx = __float2half_rn(x);
    __half hy = __float2half_rn(y);
    __half lx = __float2half_rn(x - __half2float(hx));
    __half ly = __float2half_rn(y - __half2float(hy));
    __half2 h = __halves2half2(hx, hy);
    __half2 l = __halves2half2(lx, ly);
    hi = *reinterpret_cast<uint32_t*>(&h);
    lo = *reinterpret_cast<uint32_t*>(&l);
}

__device__ __forceinline__ void mma_f16(float* c, const uint32_t* a,
                                        uint32_t b0, uint32_t b1)
{
    asm volatile(
        "mma.sync.aligned.m16n8k16.row.col.f32.f16.f16.f32 "
        "{%0,%1,%2,%3}, {%4,%5,%6,%7}, {%8,%9}, {%0,%1,%2,%3};\n"
        : "+f"(c[0]), "+f"(c[1]), "+f"(c[2]), "+f"(c[3])
        : "r"(a[0]), "r"(a[1]), "r"(a[2]), "r"(a[3]), "r"(b0), "r"(b1));
}

// ---------------------------------------------------------------------------
// GEMM (fp16x3, m16n8k16), 2-stage smem double buffer.
// C[m,n] = sum_k A[m,k]*W[n,k] + bias[n].  M=4096, N=1024, K=1024.
// Block 128x128, BK=16, 256 threads (8 warps), warp tile 32x64.
// Per iter: LDG(next) -> LDS+MMA(stage s) -> split/STS(stage s^1) -> 1 sync.
// ---------------------------------------------------------------------------
#define GSTR 12
#define GSTAGE (128 * GSTR)

__global__ __launch_bounds__(256) void gemm_f16x3(const float* __restrict__ A,
                                                  const float* __restrict__ W,
                                                  const float* __restrict__ bias,
                                                  float* __restrict__ C)
{
    const int K = 1024, N = 1024;
    __shared__ uint32_t Ah[2 * GSTAGE];
    __shared__ uint32_t Al[2 * GSTAGE];
    __shared__ uint32_t Wh[2 * GSTAGE];
    __shared__ uint32_t Wl[2 * GSTAGE];

    const int tid  = threadIdx.x;
    const int lane = tid & 31;
    const int wid  = tid >> 5;
    const int wm   = wid & 3;
    const int wn   = wid >> 2;
    const int row0 = blockIdx.y * 128;
    const int col0 = blockIdx.x * 128;
    const int g4 = lane >> 2;
    const int t4 = lane & 3;

    const int lrow = tid >> 1;          // 0..127
    const int lf   = (tid & 1) * 8;     // float k offset 0 or 8
    const int lwc  = (tid & 1) * 4;     // word col base 0 or 4

    float c[2][8][4];
    #pragma unroll
    for (int mt = 0; mt < 2; mt++)
        #pragma unroll
        for (int nt = 0; nt < 8; nt++)
            #pragma unroll
            for (int e = 0; e < 4; e++) c[mt][nt][e] = 0.f;

    const float* Aptr = A + (size_t)(row0 + lrow) * K + lf;
    const float* Wptr = W + (size_t)(col0 + lrow) * K + lf;

    // ---- prologue: iter 0 into stage 0 ----
    float4 a0 = *(const float4*)(Aptr);
    float4 a1 = *(const float4*)(Aptr + 4);
    float4 w0 = *(const float4*)(Wptr);
    float4 w1 = *(const float4*)(Wptr + 4);
    {
        uint32_t h0,h1,h2,h3, l0,l1,l2,l3;
        f16split2(a0.x, a0.y, h0, l0); f16split2(a0.z, a0.w, h1, l1);
        f16split2(a1.x, a1.y, h2, l2); f16split2(a1.z, a1.w, h3, l3);
        *(uint4*)&Ah[lrow * GSTR + lwc] = make_uint4(h0, h1, h2, h3);
        *(uint4*)&Al[lrow * GSTR + lwc] = make_uint4(l0, l1, l2, l3);
        f16split2(w0.x, w0.y, h0, l0); f16split2(w0.z, w0.w, h1, l1);
        f16split2(w1.x, w1.y, h2, l2); f16split2(w1.z, w1.w, h3, l3);
        *(uint4*)&Wh[lrow * GSTR + lwc] = make_uint4(h0, h1, h2, h3);
        *(uint4*)&Wl[lrow * GSTR + lwc] = make_uint4(l0, l1, l2, l3);
    }
    __syncthreads();

    for (int k0 = 0; k0 < K; k0 += 16) {
        const int so = ((k0 >> 4) & 1) * GSTAGE;          // read stage
        const int sn = (((k0 >> 4) + 1) & 1) * GSTAGE;    // write stage
        const bool more = (k0 + 16 < K);

        if (more) {   // LDG next iter — latency covered by MMAs below
            a0 = *(const float4*)(Aptr + k0 + 16);
            a1 = *(const float4*)(Aptr + k0 + 20);
            w0 = *(const float4*)(Wptr + k0 + 16);
            w1 = *(const float4*)(Wptr + k0 + 20);
        }

        uint32_t ah[2][4], al[2][4];
        #pragma unroll
        for (int mt = 0; mt < 2; mt++) {
            const int r = wm * 32 + mt * 16 + g4;
            ah[mt][0] = Ah[so + r * GSTR + t4];
            ah[mt][1] = Ah[so + (r + 8) * GSTR + t4];
            ah[mt][2] = Ah[so + r * GSTR + t4 + 4];
            ah[mt][3] = Ah[so + (r + 8) * GSTR + t4 + 4];
            al[mt][0] = Al[so + r * GSTR + t4];
            al[mt][1] = Al[so + (r + 8) * GSTR + t4];
            al[mt][2] = Al[so + r * GSTR + t4 + 4];
            al[mt][3] = Al[so + (r + 8) * GSTR + t4 + 4];
        }
        #pragma unroll
        for (int nt = 0; nt < 8; nt++) {
            const int cc = wn * 64 + nt * 8 + g4;
            uint32_t bh0 = Wh[so + cc * GSTR + t4];
            uint32_t bh1 = Wh[so + cc * GSTR + t4 + 4];
            uint32_t bl0 = Wl[so + cc * GSTR + t4];
            uint32_t bl1 = Wl[so + cc * GSTR + t4 + 4];
            #pragma unroll
            for (int mt = 0; mt < 2; mt++) {
                mma_f16(c[mt][nt], ah[mt], bh0, bh1);   // hi*hi
                mma_f16(c[mt][nt], al[mt], bh0, bh1);   // lo*hi
                mma_f16(c[mt][nt], ah[mt], bl0, bl1);   // hi*lo
            }
        }

        if (more) {   // split + store into other stage
            uint32_t h0,h1,h2,h3, l0,l1,l2,l3;
            f16split2(a0.x, a0.y, h0, l0); f16split2(a0.z, a0.w, h1, l1);
            f16split2(a1.x, a1.y, h2, l2); f16split2(a1.z, a1.w, h3, l3);
            *(uint4*)&Ah[sn + lrow * GSTR + lwc] = make_uint4(h0, h1, h2, h3);
            *(uint4*)&Al[sn + lrow * GSTR + lwc] = make_uint4(l0, l1, l2, l3);
            f16split2(w0.x, w0.y, h0, l0); f16split2(w0.z, w0.w, h1, l1);
            f16split2(w1.x, w1.y, h2, l2); f16split2(w1.z, w1.w, h3, l3);
            *(uint4*)&Wh[sn + lrow * GSTR + lwc] = make_uint4(h0, h1, h2, h3);
            *(uint4*)&Wl[sn + lrow * GSTR + lwc] = make_uint4(l0, l1, l2, l3);
        }
        __syncthreads();
    }

    #pragma unroll
    for (int mt = 0; mt < 2; mt++) {
        #pragma unroll
        for (int nt = 0; nt < 8; nt++) {
            int r  = row0 + wm * 32 + mt * 16 + g4;
            int cc = col0 + wn * 64 + nt * 8 + t4 * 2;
            float b0v = bias[cc], b1v = bias[cc + 1];
            C[(size_t)r * N + cc]           = c[mt][nt][0] + b0v;
            C[(size_t)r * N + cc + 1]       = c[mt][nt][1] + b1v;
            C[(size_t)(r + 8) * N + cc]     = c[mt][nt][2] + b0v;
            C[(size_t)(r + 8) * N + cc + 1] = c[mt][nt][3] + b1v;
        }
    }
}

// ---------------------------------------------------------------------------
// Tensor-core flash attention (fp16x3, m16n8k16), 2-stage K/V double buffer.
// 128q x 64k tiles, 8 warps (16 q rows each). Grid (L/128, H, B).
// m16n8 C layout == m16n8k16 A layout pairing -> P from S regs, no shuffles.
// V stored transposed [hd][key-pairs]. Word stride 36: conflict-free.
// Per tile: LDG(next) -> MMA+softmax(stage s) -> split/STS(stage s^1) -> 1 sync.
// ---------------------------------------------------------------------------
#define ASTR 36
#define Q_WORDS  (128 * ASTR)
#define KV_WORDS (64 * ASTR)
#define KVSTAGE  (4 * KV_WORDS + 128)
#define ATT_WORDS (2 * Q_WORDS + 2 * KVSTAGE)
#define ATT_SMEM  (ATT_WORDS * 4)

__global__ __launch_bounds__(256, 1) void attn_f16(const int* __restrict__ role,
                                                   const float* __restrict__ deltap)
{
    extern __shared__ uint32_t sw[];
    uint32_t* Qh = sw;
    uint32_t* Ql = Qh + Q_WORDS;
    uint32_t* kvb = Ql + Q_WORDS;   // 2 stages: [Kh | Kl | Vh | Vl | role | kpm]

    const int tid  = threadIdx.x;
    const int lane = tid & 31;
    const int w    = tid >> 5;
    const int g4   = lane >> 2;
    const int t4   = lane & 3;
    const int qt = blockIdx.x, h = blockIdx.y, b = blockIdx.z;
    const int q0 = qt * 128;
    const float delta = *deltap;
    const float scale = 0.125f;
    const size_t base = ((size_t)b * LL) * DD + (size_t)h * HDIM;
    const unsigned FULL = 0xffffffffu;

    // ---- load + split Q tile (written once, read all iterations) ----
    for (int i = tid; i < 128 * 16; i += 256) {
        int rr = i >> 4, fc = (i & 15) * 4, wc = (i & 15) * 2;
        float4 v = *(const float4*)(g_Q + base + (size_t)(q0 + rr) * DD + fc);
        uint32_t h0, l0, h1, l1;
        f16split2(v.x, v.y, h0, l0);
        f16split2(v.z, v.w, h1, l1);
        *(uint2*)&Qh[rr * ASTR + wc] = make_uint2(h0, h1);
        *(uint2*)&Ql[rr * ASTR + wc] = make_uint2(l0, l1);
    }

    const int r0  = 16 * w + g4;
    const int qg0 = q0 + r0;
    const int qg1 = qg0 + 8;
    const int rq0 = role[b * LL + qg0];
    const int rq1 = role[b * LL + qg1];

    float m0 = -INFINITY, m1 = -INFINITY, l0s = 0.f, l1s = 0.f;
    float O[8][4];
    #pragma unroll
    for (int n = 0; n < 8; n++)
        #pragma unroll
        for (int e = 0; e < 4; e++) O[n][e] = 0.f;

    // K prefetch mapping: row (tid>>4)+16p, float col (tid&15)*4
    const int krow = tid >> 4;
    const int kfc  = (tid & 15) * 4;
    const int kwc  = (tid & 15) * 2;
    // V prefetch mapping: key-pair r = tid&31, hd group c = (tid>>5)+8*it
    const int vr  = tid & 31;
    const int vc0 = tid >> 5;

    const int ntiles = 2 * qt + 2;

    float4 kpre[4], vpre[4];
    int rpre = 0, kppre = 0;

    // ---- prologue: tile 0 -> stage 0 ----
    #pragma unroll
    for (int p = 0; p < 4; p++)
        kpre[p] = *(const float4*)(g_K + base + (size_t)(krow + 16 * p) * DD + kfc);
    #pragma unroll
    for (int it = 0; it < 2; it++) {
        const int c = vc0 + 8 * it;
        vpre[2 * it]     = *(const float4*)(g_V + base + (size_t)(2 * vr) * DD + 4 * c);
        vpre[2 * it + 1] = *(const float4*)(g_V + base + (size_t)(2 * vr + 1) * DD + 4 * c);
    }
    if (tid < 64) { rpre = role[b * LL + tid]; kppre = g_kpm[b * LL + tid]; }
    {
        uint32_t* Kh0 = kvb;
        uint32_t* Kl0 = Kh0 + KV_WORDS;
        uint32_t* Vh0 = Kl0 + KV_WORDS;
        uint32_t* Vl0 = Vh0 + KV_WORDS;
        int* roleK0 = (int*)(Vl0 + KV_WORDS);
        int* kpmK0  = roleK0 + 64;
        #pragma unroll
        for (int p = 0; p < 4; p++) {
            const int rr = krow + 16 * p;
            uint32_t h0, l0, h1, l1;
            f16split2(kpre[p].x, kpre[p].y, h0, l0);
            f16split2(kpre[p].z, kpre[p].w, h1, l1);
            *(uint2*)&Kh0[rr * ASTR + kwc] = make_uint2(h0, h1);
            *(uint2*)&Kl0[rr * ASTR + kwc] = make_uint2(l0, l1);
        }
        #pragma unroll
        for (int it = 0; it < 2; it++) {
            const int c = vc0 + 8 * it;
            const float* v0 = (const float*)&vpre[2 * it];
            const float* v1 = (const float*)&vpre[2 * it + 1];
            #pragma unroll
            for (int i = 0; i < 4; i++) {
                uint32_t hw, lw;
                f16split2(v0[i], v1[i], hw, lw);
                Vh0[(4 * c + i) * ASTR + vr] = hw;
                Vl0[(4 * c + i) * ASTR + vr] = lw;
            }
        }
        if (tid < 64) { roleK0[tid] = rpre; kpmK0[tid] = kppre; }
    }
    __syncthreads();

    for (int t = 0; t < ntiles; t++) {
        const int k0t = t * 64;
        const bool more = (t + 1 < ntiles);

        uint32_t* Kh = kvb + (t & 1) * KVSTAGE;
        uint32_t* Kl = Kh + KV_WORDS;
        uint32_t* Vh = Kl + KV_WORDS;
        uint32_t* Vl = Vh + KV_WORDS;
        const int* roleK = (const int*)(Vl + KV_WORDS);
        const int* kpmK  = roleK + 64;

        // ---- LDG next tile (latency covered by compute below) ----
        if (more) {
            const int kn = k0t + 64;
            #pragma unroll
            for (int p = 0; p < 4; p++)
                kpre[p] = *(const float4*)(g_K + base + (size_t)(kn + krow + 16 * p) * DD + kfc);
            #pragma unroll
            for (int it = 0; it < 2; it++) {
                const int c = vc0 + 8 * it;
                vpre[2 * it]     = *(const float4*)(g_V + base + (size_t)(kn + 2 * vr) * DD + 4 * c);
                vpre[2 * it + 1] = *(const float4*)(g_V + base + (size_t)(kn + 2 * vr + 1) * DD + 4 * c);
            }
            if (tid < 64) { rpre = role[b * LL + kn + tid]; kppre = g_kpm[b * LL + kn + tid]; }
        }

        // ---- S = Q K^T ----
        float sc[8][4];
        #pragma unroll
        for (int j = 0; j < 8; j++)
            #pragma unroll
            for (int e = 0; e < 4; e++) sc[j][e] = 0.f;

        #pragma unroll
        for (int ks = 0; ks < 4; ks++) {
            const int kc = 8 * ks + t4;
            uint32_t ah[4], al[4];
            ah[0] = Qh[r0 * ASTR + kc];
            ah[1] = Qh[(r0 + 8) * ASTR + kc];
            ah[2] = Qh[r0 * ASTR + kc + 4];
            ah[3] = Qh[(r0 + 8) * ASTR + kc + 4];
            al[0] = Ql[r0 * ASTR + kc];
            al[1] = Ql[(r0 + 8) * ASTR + kc];
            al[2] = Ql[r0 * ASTR + kc + 4];
            al[3] = Ql[(r0 + 8) * ASTR + kc + 4];
            #pragma unroll
            for (int j = 0; j < 8; j++) {
                const int kr = 8 * j + g4;
                uint32_t bh0 = Kh[kr * ASTR + kc];
                uint32_t bh1 = Kh[kr * ASTR + kc + 4];
                uint32_t bl0 = Kl[kr * ASTR + kc];
                uint32_t bl1 = Kl[kr * ASTR + kc + 4];
                mma_f16(sc[j], ah, bh0, bh1);
                mma_f16(sc[j], al, bh0, bh1);
                mma_f16(sc[j], ah, bl0, bl1);
            }
        }

        // ---- scale + role bias + masks, online softmax ----
        float mx0 = -INFINITY, mx1 = -INFINITY;
        #pragma unroll
        for (int j = 0; j < 8; j++) {
            const int c0 = 8 * j + 2 * t4;
            const int rl0 = roleK[c0], rl1 = roleK[c0 + 1];
            const int kp0 = kpmK[c0],  kp1 = kpmK[c0 + 1];
            const int ky0 = k0t + c0,  ky1 = ky0 + 1;
            float s00 = sc[j][0] * scale + ((rq0 == rl0) ? delta : 0.f);
            float s01 = sc[j][1] * scale + ((rq0 == rl1) ? delta : 0.f);
            float s10 = sc[j][2] * scale + ((rq1 == rl0) ? delta : 0.f);
            float s11 = sc[j][3] * scale + ((rq1 == rl1) ? delta : 0.f);
            if (ky0 > qg0 || kp0) s00 = -INFINITY;
            if (ky1 > qg0 || kp1) s01 = -INFINITY;
            if (ky0 > qg1 || kp0) s10 = -INFINITY;
            if (ky1 > qg1 || kp1) s11 = -INFINITY;
            sc[j][0] = s00; sc[j][1] = s01; sc[j][2] = s10; sc[j][3] = s11;
            mx0 = fmaxf(mx0, fmaxf(s00, s01));
            mx1 = fmaxf(mx1, fmaxf(s10, s11));
        }
        mx0 = fmaxf(mx0, __shfl_xor_sync(FULL, mx0, 1));
        mx0 = fmaxf(mx0, __shfl_xor_sync(FULL, mx0, 2));
        mx1 = fmaxf(mx1, __shfl_xor_sync(FULL, mx1, 1));
        mx1 = fmaxf(mx1, __shfl_xor_sync(FULL, mx1, 2));

        const float mn0 = fmaxf(m0, mx0);
        const float mn1 = fmaxf(m1, mx1);
        const bool z0 = (mn0 == -INFINITY);
        const bool z1 = (mn1 == -INFINITY);
        const float alpha0 = z0 ? 1.f : __expf(m0 - mn0);
        const float alpha1 = z1 ? 1.f : __expf(m1 - mn1);
        float ps0 = 0.f, ps1 = 0.f;
        #pragma unroll
        for (int j = 0; j < 8; j++) {
            float p;
            p = z0 ? 0.f : __expf(sc[j][0] - mn0); sc[j][0] = p; ps0 += p;
            p = z0 ? 0.f : __expf(sc[j][1] - mn0); sc[j][1] = p; ps0 += p;
            p = z1 ? 0.f : __expf(sc[j][2] - mn1); sc[j][2] = p; ps1 += p;
            p = z1 ? 0.f : __expf(sc[j][3] - mn1); sc[j][3] = p; ps1 += p;
        }
        ps0 += __shfl_xor_sync(FULL, ps0, 1);
        ps0 += __shfl_xor_sync(FULL, ps0, 2);
        ps1 += __shfl_xor_sync(FULL, ps1, 1);
        ps1 += __shfl_xor_sync(FULL, ps1, 2);
        l0s = l0s * alpha0 + ps0;  m0 = mn0;
        l1s = l1s * alpha1 + ps1;  m1 = mn1;

        #pragma unroll
        for (int n = 0; n < 8; n++) {
            O[n][0] *= alpha0; O[n][1] *= alpha0;
            O[n][2] *= alpha1; O[n][3] *= alpha1;
        }

        // ---- O += P V : P fragments directly from S accumulators ----
        #pragma unroll
        for (int c = 0; c < 4; c++) {
            uint32_t ph[4], pl[4];
            f16split2(sc[2 * c][0],     sc[2 * c][1],     ph[0], pl[0]);
            f16split2(sc[2 * c][2],     sc[2 * c][3],     ph[1], pl[1]);
            f16split2(sc[2 * c + 1][0], sc[2 * c + 1][1], ph[2], pl[2]);
            f16split2(sc[2 * c + 1][2], sc[2 * c + 1][3], ph[3], pl[3]);
            #pragma unroll
            for (int n = 0; n < 8; n++) {
                const int vcc = 8 * n + g4;
                uint32_t bh0 = Vh[vcc * ASTR + 8 * c + t4];
                uint32_t bh1 = Vh[vcc * ASTR + 8 * c + t4 + 4];
                uint32_t bl0 = Vl[vcc * ASTR + 8 * c + t4];
                uint32_t bl1 = Vl[vcc * ASTR + 8 * c + t4 + 4];
                mma_f16(O[n], ph, bh0, bh1);
                mma_f16(O[n], pl, bh0, bh1);
                mma_f16(O[n], ph, bl0, bl1);
            }
        }

        // ---- split/store next tile into other stage, then ONE sync ----
        if (more) {
            uint32_t* nKh = kvb + ((t + 1) & 1) * KVSTAGE;
            uint32_t* nKl = nKh + KV_WORDS;
            uint32_t* nVh = nKl + KV_WORDS;
            uint32_t* nVl = nVh + KV_WORDS;
            int* nroleK = (int*)(nVl + KV_WORDS);
            int* nkpmK  = nroleK + 64;
            #pragma unroll
            for (int p = 0; p < 4; p++) {
                const int rr = krow + 16 * p;
                uint32_t h0, l0, h1, l1;
                f16split2(kpre[p].x, kpre[p].y, h0, l0);
                f16split2(kpre[p].z, kpre[p].w, h1, l1);
                *(uint2*)&nKh[rr * ASTR + kwc] = make_uint2(h0, h1);
                *(uint2*)&nKl[rr * ASTR + kwc] = make_uint2(l0, l1);
            }
            #pragma unroll
            for (int it = 0; it < 2; it++) {
                const int c = vc0 + 8 * it;
                const float* v0 = (const float*)&vpre[2 * it];
                const float* v1 = (const float*)&vpre[2 * it + 1];
                #pragma unroll
                for (int i = 0; i < 4; i++) {
                    uint32_t hw, lw;
                    f16split2(v0[i], v1[i], hw, lw);
                    nVh[(4 * c + i) * ASTR + vr] = hw;
                    nVl[(4 * c + i) * ASTR + vr] = lw;
                }
            }
            if (tid < 64) { nroleK[tid] = rpre; nkpmK[tid] = kppre; }
            __syncthreads();
        }
    }

    // ---- normalize + store ----
    const float i0 = (l0s > 0.f) ? (1.f / l0s) : 0.f;
    const float i1 = (l1s > 0.f) ? (1.f / l1s) : 0.f;
    #pragma unroll
    for (int n = 0; n < 8; n++) {
        float2 o0, o1;
        o0.x = O[n][0] * i0; o0.y = O[n][1] * i0;
        o1.x = O[n][2] * i1; o1.y = O[n][3] * i1;
        *(float2*)(g_A + base + (size_t)qg0 * DD + 8 * n + 2 * t4) = o0;
        *(float2*)(g_A + base + (size_t)qg1 * DD + 8 * n + 2 * t4) = o1;
    }
}

// ---------------------------------------------------------------------------
// Launch
// ---------------------------------------------------------------------------
extern "C" void kernel_launch(void* const* d_in, const int* in_sizes, int n_in,
                              void* d_out, int out_size)
{
    const float* x    = (const float*)d_in[0];
    const int*   role = (const int*)d_in[1];
    const int*   kpm_raw = (const int*)d_in[3];
    const float* Wq = (const float*)d_in[4];
    const float* bq = (const float*)d_in[5];
    const float* Wk = (const float*)d_in[6];
    const float* bk = (const float*)d_in[7];
    const float* Wv = (const float*)d_in[8];
    const float* bv = (const float*)d_in[9];
    const float* Wo = (const float*)d_in[10];
    const float* bo = (const float*)d_in[11];
    const float* delta = (const float*)d_in[12];

    float *qb, *kb, *vb, *ab;
    cudaGetSymbolAddress((void**)&qb, g_Q);
    cudaGetSymbolAddress((void**)&kb, g_K);
    cudaGetSymbolAddress((void**)&vb, g_V);
    cudaGetSymbolAddress((void**)&ab, g_A);

    cudaFuncSetAttribute(attn_f16,
                         cudaFuncAttributeMaxDynamicSharedMemorySize, ATT_SMEM);

    normalize_kpm<<<1, 256>>>(kpm_raw);

    dim3 ggrid(1024 / 128, MROWS / 128);   // (8, 32)
    gemm_f16x3<<<ggrid, 256>>>(x, Wq, bq, qb);
    gemm_f16x3<<<ggrid, 256>>>(x, Wk, bk, kb);
    gemm_f16x3<<<ggrid, 256>>>(x, Wv, bv, vb);

    dim3 agrid(LL / 128, HH, BB);          // (16, 16, 2)
    attn_f16<<<agrid, 256, ATT_SMEM>>>(role, delta);

    gemm_f16x3<<<ggrid, 256>>>(ab, Wo, bo, (float*)d_out);
}

// round 15
// speedup vs baseline: 1.0533x; 1.0533x over previous
#include <cuda_runtime.h>
#include <cuda_bf16.h>
#include <cuda_fp16.h>
#include <math.h>
#include <stdint.h>

#define BB 2
#define LL 2048
#define DD 1024
#define HH 16
#define HDIM 64
#define MROWS (BB*LL)   // 4096

// Scratch (allocation-free per harness rules)
static __device__ float g_Q[MROWS * DD];
static __device__ float g_K[MROWS * DD];
static __device__ float g_V[MROWS * DD];
static __device__ float g_A[MROWS * DD];
static __device__ int   g_kpm[BB * LL];

// ---------------------------------------------------------------------------
// Normalize key_padding_mask regardless of on-disk dtype (validated R9-R14).
// ---------------------------------------------------------------------------
__global__ void normalize_kpm(const int* __restrict__ raw)
{
    __shared__ int ok_int, ok_float;
    int tid = threadIdx.x;
    if (tid == 0) { ok_int = 1; ok_float = 1; }
    __syncthreads();
    for (int i = tid; i < BB * LL; i += blockDim.x) {
        int v = raw[i];
        if (v != 0 && v != 1)          ok_int = 0;
        if (v != 0 && v != 0x3F800000) ok_float = 0;
    }
    __syncthreads();
    const unsigned char* raw8 = (const unsigned char*)raw;
    for (int i = tid; i < BB * LL; i += blockDim.x) {
        int out;
        if (ok_int)        out = raw[i];
        else if (ok_float) out = raw[i] ? 1 : 0;
        else               out = raw8[i] ? 1 : 0;
        g_kpm[i] = out;
    }
}

// ---------------------------------------------------------------------------
// fp16 split helpers: x = hi + lo, both fp16 (11-bit mantissa each;
// residual structure ~2^-22 per product, like tf32x3).
// ---------------------------------------------------------------------------
__device__ __forceinline__ void f16split2(float x, float y, uint32_t& hi, uint32_t& lo)
{
    __half hx = __float2half_rn(x);
    __half hy = __float2half_rn(y);
    __half lx = __float2half_rn(x - __half2float(hx));
    __half ly = __float2half_rn(y - __half2float(hy));
    __half2 h = __halves2half2(hx, hy);
    __half2 l = __halves2half2(lx, ly);
    hi = *reinterpret_cast<uint32_t*>(&h);
    lo = *reinterpret_cast<uint32_t*>(&l);
}

__device__ __forceinline__ void mma_f16(float* c, const uint32_t* a,
                                        uint32_t b0, uint32_t b1)
{
    asm volatile(
        "mma.sync.aligned.m16n8k16.row.col.f32.f16.f16.f32 "
        "{%0,%1,%2,%3}, {%4,%5,%6,%7}, {%8,%9}, {%0,%1,%2,%3};\n"
        : "+f"(c[0]), "+f"(c[1]), "+f"(c[2]), "+f"(c[3])
        : "r"(a[0]), "r"(a[1]), "r"(a[2]), "r"(a[3]), "r"(b0), "r"(b1));
}

// ---------------------------------------------------------------------------
// GEMM (fp16x3, m16n8k16), 2-stage smem double buffer, z-fused weights.
// C_z[m,n] = sum_k A[m,k]*W_z[n,k] + b_z[n].  M=4096, N=1024, K=1024.
// Block 128x128, BK=16, 256 threads (8 warps), warp tile 32x64.
// blockIdx.z picks (W, bias, C) -> one launch covers Q,K,V projections:
// 768 balanced CTAs at 2 CTAs/SM instead of 3 lopsided 256-CTA launches.
// ---------------------------------------------------------------------------
#define GSTR 12
#define GSTAGE (128 * GSTR)

__global__ __launch_bounds__(256, 2) void gemm_f16x3z(
    const float* __restrict__ A,
    const float* __restrict__ W0, const float* __restrict__ b0p, float* __restrict__ C0,
    const float* __restrict__ W1, const float* __restrict__ b1p, float* __restrict__ C1,
    const float* __restrict__ W2, const float* __restrict__ b2p, float* __restrict__ C2)
{
    const int K = 1024, N = 1024;
    __shared__ uint32_t Ah[2 * GSTAGE];
    __shared__ uint32_t Al[2 * GSTAGE];
    __shared__ uint32_t Wh[2 * GSTAGE];
    __shared__ uint32_t Wl[2 * GSTAGE];

    const int z = blockIdx.z;
    const float* W    = (z == 0) ? W0 : (z == 1) ? W1 : W2;
    const float* bias = (z == 0) ? b0p : (z == 1) ? b1p : b2p;
    float*       C    = (z == 0) ? C0 : (z == 1) ? C1 : C2;

    const int tid  = threadIdx.x;
    const int lane = tid & 31;
    const int wid  = tid >> 5;
    const int wm   = wid & 3;
    const int wn   = wid >> 2;
    const int row0 = blockIdx.y * 128;
    const int col0 = blockIdx.x * 128;
    const int g4 = lane >> 2;
    const int t4 = lane & 3;

    const int lrow = tid >> 1;          // 0..127
    const int lf   = (tid & 1) * 8;     // float k offset 0 or 8
    const int lwc  = (tid & 1) * 4;     // word col base 0 or 4

    float c[2][8][4];
    #pragma unroll
    for (int mt = 0; mt < 2; mt++)
        #pragma unroll
        for (int nt = 0; nt < 8; nt++)
            #pragma unroll
            for (int e = 0; e < 4; e++) c[mt][nt][e] = 0.f;

    const float* Aptr = A + (size_t)(row0 + lrow) * K + lf;
    const float* Wptr = W + (size_t)(col0 + lrow) * K + lf;

    // ---- prologue: iter 0 into stage 0 ----
    float4 a0 = *(const float4*)(Aptr);
    float4 a1 = *(const float4*)(Aptr + 4);
    float4 w0 = *(const float4*)(Wptr);
    float4 w1 = *(const float4*)(Wptr + 4);
    {
        uint32_t h0,h1,h2,h3, l0,l1,l2,l3;
        f16split2(a0.x, a0.y, h0, l0); f16split2(a0.z, a0.w, h1, l1);
        f16split2(a1.x, a1.y, h2, l2); f16split2(a1.z, a1.w, h3, l3);
        *(uint4*)&Ah[lrow * GSTR + lwc] = make_uint4(h0, h1, h2, h3);
        *(uint4*)&Al[lrow * GSTR + lwc] = make_uint4(l0, l1, l2, l3);
        f16split2(w0.x, w0.y, h0, l0); f16split2(w0.z, w0.w, h1, l1);
        f16split2(w1.x, w1.y, h2, l2); f16split2(w1.z, w1.w, h3, l3);
        *(uint4*)&Wh[lrow * GSTR + lwc] = make_uint4(h0, h1, h2, h3);
        *(uint4*)&Wl[lrow * GSTR + lwc] = make_uint4(l0, l1, l2, l3);
    }
    __syncthreads();

    for (int k0 = 0; k0 < K; k0 += 16) {
        const int so = ((k0 >> 4) & 1) * GSTAGE;          // read stage
        const int sn = (((k0 >> 4) + 1) & 1) * GSTAGE;    // write stage
        const bool more = (k0 + 16 < K);

        if (more) {   // LDG next iter — latency covered by MMAs below
            a0 = *(const float4*)(Aptr + k0 + 16);
            a1 = *(const float4*)(Aptr + k0 + 20);
            w0 = *(const float4*)(Wptr + k0 + 16);
            w1 = *(const float4*)(Wptr + k0 + 20);
        }

        uint32_t ah[2][4], al[2][4];
        #pragma unroll
        for (int mt = 0; mt < 2; mt++) {
            const int r = wm * 32 + mt * 16 + g4;
            ah[mt][0] = Ah[so + r * GSTR + t4];
            ah[mt][1] = Ah[so + (r + 8) * GSTR + t4];
            ah[mt][2] = Ah[so + r * GSTR + t4 + 4];
            ah[mt][3] = Ah[so + (r + 8) * GSTR + t4 + 4];
            al[mt][0] = Al[so + r * GSTR + t4];
            al[mt][1] = Al[so + (r + 8) * GSTR + t4];
            al[mt][2] = Al[so + r * GSTR + t4 + 4];
            al[mt][3] = Al[so + (r + 8) * GSTR + t4 + 4];
        }
        #pragma unroll
        for (int nt = 0; nt < 8; nt++) {
            const int cc = wn * 64 + nt * 8 + g4;
            uint32_t bh0 = Wh[so + cc * GSTR + t4];
            uint32_t bh1 = Wh[so + cc * GSTR + t4 + 4];
            uint32_t bl0 = Wl[so + cc * GSTR + t4];
            uint32_t bl1 = Wl[so + cc * GSTR + t4 + 4];
            #pragma unroll
            for (int mt = 0; mt < 2; mt++) {
                mma_f16(c[mt][nt], ah[mt], bh0, bh1);   // hi*hi
                mma_f16(c[mt][nt], al[mt], bh0, bh1);   // lo*hi
                mma_f16(c[mt][nt], ah[mt], bl0, bl1);   // hi*lo
            }
        }

        if (more) {   // split + store into other stage
            uint32_t h0,h1,h2,h3, l0,l1,l2,l3;
            f16split2(a0.x, a0.y, h0, l0); f16split2(a0.z, a0.w, h1, l1);
            f16split2(a1.x, a1.y, h2, l2); f16split2(a1.z, a1.w, h3, l3);
            *(uint4*)&Ah[sn + lrow * GSTR + lwc] = make_uint4(h0, h1, h2, h3);
            *(uint4*)&Al[sn + lrow * GSTR + lwc] = make_uint4(l0, l1, l2, l3);
            f16split2(w0.x, w0.y, h0, l0); f16split2(w0.z, w0.w, h1, l1);
            f16split2(w1.x, w1.y, h2, l2); f16split2(w1.z, w1.w, h3, l3);
            *(uint4*)&Wh[sn + lrow * GSTR + lwc] = make_uint4(h0, h1, h2, h3);
            *(uint4*)&Wl[sn + lrow * GSTR + lwc] = make_uint4(l0, l1, l2, l3);
        }
        __syncthreads();
    }

    #pragma unroll
    for (int mt = 0; mt < 2; mt++) {
        #pragma unroll
        for (int nt = 0; nt < 8; nt++) {
            int r  = row0 + wm * 32 + mt * 16 + g4;
            int cc = col0 + wn * 64 + nt * 8 + t4 * 2;
            float b0v = bias[cc], b1v = bias[cc + 1];
            C[(size_t)r * N + cc]           = c[mt][nt][0] + b0v;
            C[(size_t)r * N + cc + 1]       = c[mt][nt][1] + b1v;
            C[(size_t)(r + 8) * N + cc]     = c[mt][nt][2] + b0v;
            C[(size_t)(r + 8) * N + cc + 1] = c[mt][nt][3] + b1v;
        }
    }
}

// ---------------------------------------------------------------------------
// Tensor-core flash attention (fp16x3, m16n8k16), 2-stage K/V double buffer.
// 128q x 64k tiles, 8 warps (16 q rows each). Grid (L/128, H, B).
// launch_bounds(256,2): regs <=128 so 2 CTAs co-reside (smem 109KB x2 fits).
// ---------------------------------------------------------------------------
#define ASTR 36
#define Q_WORDS  (128 * ASTR)
#define KV_WORDS (64 * ASTR)
#define KVSTAGE  (4 * KV_WORDS + 128)
#define ATT_WORDS (2 * Q_WORDS + 2 * KVSTAGE)
#define ATT_SMEM  (ATT_WORDS * 4)

__global__ __launch_bounds__(256, 2) void attn_f16(const int* __restrict__ role,
                                                   const float* __restrict__ deltap)
{
    extern __shared__ uint32_t sw[];
    uint32_t* Qh = sw;
    uint32_t* Ql = Qh + Q_WORDS;
    uint32_t* kvb = Ql + Q_WORDS;   // 2 stages: [Kh | Kl | Vh | Vl | role | kpm]

    const int tid  = threadIdx.x;
    const int lane = tid & 31;
    const int w    = tid >> 5;
    const int g4   = lane >> 2;
    const int t4   = lane & 3;
    const int qt = blockIdx.x, h = blockIdx.y, b = blockIdx.z;
    const int q0 = qt * 128;
    const float delta = *deltap;
    const float scale = 0.125f;
    const size_t base = ((size_t)b * LL) * DD + (size_t)h * HDIM;
    const unsigned FULL = 0xffffffffu;

    // ---- load + split Q tile (written once, read all iterations) ----
    for (int i = tid; i < 128 * 16; i += 256) {
        int rr = i >> 4, fc = (i & 15) * 4, wc = (i & 15) * 2;
        float4 v = *(const float4*)(g_Q + base + (size_t)(q0 + rr) * DD + fc);
        uint32_t h0, l0, h1, l1;
        f16split2(v.x, v.y, h0, l0);
        f16split2(v.z, v.w, h1, l1);
        *(uint2*)&Qh[rr * ASTR + wc] = make_uint2(h0, h1);
        *(uint2*)&Ql[rr * ASTR + wc] = make_uint2(l0, l1);
    }

    const int r0  = 16 * w + g4;
    const int qg0 = q0 + r0;
    const int qg1 = qg0 + 8;
    const int rq0 = role[b * LL + qg0];
    const int rq1 = role[b * LL + qg1];

    float m0 = -INFINITY, m1 = -INFINITY, l0s = 0.f, l1s = 0.f;
    float O[8][4];
    #pragma unroll
    for (int n = 0; n < 8; n++)
        #pragma unroll
        for (int e = 0; e < 4; e++) O[n][e] = 0.f;

    const int krow = tid >> 4;
    const int kfc  = (tid & 15) * 4;
    const int kwc  = (tid & 15) * 2;
    const int vr  = tid & 31;
    const int vc0 = tid >> 5;

    const int ntiles = 2 * qt + 2;

    float4 kpre[4], vpre[4];
    int rpre = 0, kppre = 0;

    // ---- prologue: tile 0 -> stage 0 ----
    #pragma unroll
    for (int p = 0; p < 4; p++)
        kpre[p] = *(const float4*)(g_K + base + (size_t)(krow + 16 * p) * DD + kfc);
    #pragma unroll
    for (int it = 0; it < 2; it++) {
        const int c = vc0 + 8 * it;
        vpre[2 * it]     = *(const float4*)(g_V + base + (size_t)(2 * vr) * DD + 4 * c);
        vpre[2 * it + 1] = *(const float4*)(g_V + base + (size_t)(2 * vr + 1) * DD + 4 * c);
    }
    if (tid < 64) { rpre = role[b * LL + tid]; kppre = g_kpm[b * LL + tid]; }
    {
        uint32_t* Kh0 = kvb;
        uint32_t* Kl0 = Kh0 + KV_WORDS;
        uint32_t* Vh0 = Kl0 + KV_WORDS;
        uint32_t* Vl0 = Vh0 + KV_WORDS;
        int* roleK0 = (int*)(Vl0 + KV_WORDS);
        int* kpmK0  = roleK0 + 64;
        #pragma unroll
        for (int p = 0; p < 4; p++) {
            const int rr = krow + 16 * p;
            uint32_t h0, l0, h1, l1;
            f16split2(kpre[p].x, kpre[p].y, h0, l0);
            f16split2(kpre[p].z, kpre[p].w, h1, l1);
            *(uint2*)&Kh0[rr * ASTR + kwc] = make_uint2(h0, h1);
            *(uint2*)&Kl0[rr * ASTR + kwc] = make_uint2(l0, l1);
        }
        #pragma unroll
        for (int it = 0; it < 2; it++) {
            const int c = vc0 + 8 * it;
            const float* v0 = (const float*)&vpre[2 * it];
            const float* v1 = (const float*)&vpre[2 * it + 1];
            #pragma unroll
            for (int i = 0; i < 4; i++) {
                uint32_t hw, lw;
                f16split2(v0[i], v1[i], hw, lw);
                Vh0[(4 * c + i) * ASTR + vr] = hw;
                Vl0[(4 * c + i) * ASTR + vr] = lw;
            }
        }
        if (tid < 64) { roleK0[tid] = rpre; kpmK0[tid] = kppre; }
    }
    __syncthreads();

    for (int t = 0; t < ntiles; t++) {
        const int k0t = t * 64;
        const bool more = (t + 1 < ntiles);

        uint32_t* Kh = kvb + (t & 1) * KVSTAGE;
        uint32_t* Kl = Kh + KV_WORDS;
        uint32_t* Vh = Kl + KV_WORDS;
        uint32_t* Vl = Vh + KV_WORDS;
        const int* roleK = (const int*)(Vl + KV_WORDS);
        const int* kpmK  = roleK + 64;

        // ---- LDG next tile (latency covered by compute below) ----
        if (more) {
            const int kn = k0t + 64;
            #pragma unroll
            for (int p = 0; p < 4; p++)
                kpre[p] = *(const float4*)(g_K + base + (size_t)(kn + krow + 16 * p) * DD + kfc);
            #pragma unroll
            for (int it = 0; it < 2; it++) {
                const int c = vc0 + 8 * it;
                vpre[2 * it]     = *(const float4*)(g_V + base + (size_t)(kn + 2 * vr) * DD + 4 * c);
                vpre[2 * it + 1] = *(const float4*)(g_V + base + (size_t)(kn + 2 * vr + 1) * DD + 4 * c);
            }
            if (tid < 64) { rpre = role[b * LL + kn + tid]; kppre = g_kpm[b * LL + kn + tid]; }
        }

        // ---- S = Q K^T ----
        float sc[8][4];
        #pragma unroll
        for (int j = 0; j < 8; j++)
            #pragma unroll
            for (int e = 0; e < 4; e++) sc[j][e] = 0.f;

        #pragma unroll
        for (int ks = 0; ks < 4; ks++) {
            const int kc = 8 * ks + t4;
            uint32_t ah[4], al[4];
            ah[0] = Qh[r0 * ASTR + kc];
            ah[1] = Qh[(r0 + 8) * ASTR + kc];
            ah[2] = Qh[r0 * ASTR + kc + 4];
            ah[3] = Qh[(r0 + 8) * ASTR + kc + 4];
            al[0] = Ql[r0 * ASTR + kc];
            al[1] = Ql[(r0 + 8) * ASTR + kc];
            al[2] = Ql[r0 * ASTR + kc + 4];
            al[3] = Ql[(r0 + 8) * ASTR + kc + 4];
            #pragma unroll
            for (int j = 0; j < 8; j++) {
                const int kr = 8 * j + g4;
                uint32_t bh0 = Kh[kr * ASTR + kc];
                uint32_t bh1 = Kh[kr * ASTR + kc + 4];
                uint32_t bl0 = Kl[kr * ASTR + kc];
                uint32_t bl1 = Kl[kr * ASTR + kc + 4];
                mma_f16(sc[j], ah, bh0, bh1);
                mma_f16(sc[j], al, bh0, bh1);
                mma_f16(sc[j], ah, bl0, bl1);
            }
        }

        // ---- scale + role bias + masks, online softmax ----
        float mx0 = -INFINITY, mx1 = -INFINITY;
        #pragma unroll
        for (int j = 0; j < 8; j++) {
            const int c0 = 8 * j + 2 * t4;
            const int rl0 = roleK[c0], rl1 = roleK[c0 + 1];
            const int kp0 = kpmK[c0],  kp1 = kpmK[c0 + 1];
            const int ky0 = k0t + c0,  ky1 = ky0 + 1;
            float s00 = sc[j][0] * scale + ((rq0 == rl0) ? delta : 0.f);
            float s01 = sc[j][1] * scale + ((rq0 == rl1) ? delta : 0.f);
            float s10 = sc[j][2] * scale + ((rq1 == rl0) ? delta : 0.f);
            float s11 = sc[j][3] * scale + ((rq1 == rl1) ? delta : 0.f);
            if (ky0 > qg0 || kp0) s00 = -INFINITY;
            if (ky1 > qg0 || kp1) s01 = -INFINITY;
            if (ky0 > qg1 || kp0) s10 = -INFINITY;
            if (ky1 > qg1 || kp1) s11 = -INFINITY;
            sc[j][0] = s00; sc[j][1] = s01; sc[j][2] = s10; sc[j][3] = s11;
            mx0 = fmaxf(mx0, fmaxf(s00, s01));
            mx1 = fmaxf(mx1, fmaxf(s10, s11));
        }
        mx0 = fmaxf(mx0, __shfl_xor_sync(FULL, mx0, 1));
        mx0 = fmaxf(mx0, __shfl_xor_sync(FULL, mx0, 2));
        mx1 = fmaxf(mx1, __shfl_xor_sync(FULL, mx1, 1));
        mx1 = fmaxf(mx1, __shfl_xor_sync(FULL, mx1, 2));

        const float mn0 = fmaxf(m0, mx0);
        const float mn1 = fmaxf(m1, mx1);
        const bool z0 = (mn0 == -INFINITY);
        const bool z1 = (mn1 == -INFINITY);
        const float alpha0 = z0 ? 1.f : __expf(m0 - mn0);
        const float alpha1 = z1 ? 1.f : __expf(m1 - mn1);
        float ps0 = 0.f, ps1 = 0.f;
        #pragma unroll
        for (int j = 0; j < 8; j++) {
            float p;
            p = z0 ? 0.f : __expf(sc[j][0] - mn0); sc[j][0] = p; ps0 += p;
            p = z0 ? 0.f : __expf(sc[j][1] - mn0); sc[j][1] = p; ps0 += p;
            p = z1 ? 0.f : __expf(sc[j][2] - mn1); sc[j][2] = p; ps1 += p;
            p = z1 ? 0.f : __expf(sc[j][3] - mn1); sc[j][3] = p; ps1 += p;
        }
        ps0 += __shfl_xor_sync(FULL, ps0, 1);
        ps0 += __shfl_xor_sync(FULL, ps0, 2);
        ps1 += __shfl_xor_sync(FULL, ps1, 1);
        ps1 += __shfl_xor_sync(FULL, ps1, 2);
        l0s = l0s * alpha0 + ps0;  m0 = mn0;
        l1s = l1s * alpha1 + ps1;  m1 = mn1;

        #pragma unroll
        for (int n = 0; n < 8; n++) {
            O[n][0] *= alpha0; O[n][1] *= alpha0;
            O[n][2] *= alpha1; O[n][3] *= alpha1;
        }

        // ---- O += P V : P fragments directly from S accumulators ----
        #pragma unroll
        for (int c = 0; c < 4; c++) {
            uint32_t ph[4], pl[4];
            f16split2(sc[2 * c][0],     sc[2 * c][1],     ph[0], pl[0]);
            f16split2(sc[2 * c][2],     sc[2 * c][3],     ph[1], pl[1]);
            f16split2(sc[2 * c + 1][0], sc[2 * c + 1][1], ph[2], pl[2]);
            f16split2(sc[2 * c + 1][2], sc[2 * c + 1][3], ph[3], pl[3]);
            #pragma unroll
            for (int n = 0; n < 8; n++) {
                const int vcc = 8 * n + g4;
                uint32_t bh0 = Vh[vcc * ASTR + 8 * c + t4];
                uint32_t bh1 = Vh[vcc * ASTR + 8 * c + t4 + 4];
                uint32_t bl0 = Vl[vcc * ASTR + 8 * c + t4];
                uint32_t bl1 = Vl[vcc * ASTR + 8 * c + t4 + 4];
                mma_f16(O[n], ph, bh0, bh1);
                mma_f16(O[n], pl, bh0, bh1);
                mma_f16(O[n], ph, bl0, bl1);
            }
        }

        // ---- split/store next tile into other stage, then ONE sync ----
        if (more) {
            uint32_t* nKh = kvb + ((t + 1) & 1) * KVSTAGE;
            uint32_t* nKl = nKh + KV_WORDS;
            uint32_t* nVh = nKl + KV_WORDS;
            uint32_t* nVl = nVh + KV_WORDS;
            int* nroleK = (int*)(nVl + KV_WORDS);
            int* nkpmK  = nroleK + 64;
            #pragma unroll
            for (int p = 0; p < 4; p++) {
                const int rr = krow + 16 * p;
                uint32_t h0, l0, h1, l1;
                f16split2(kpre[p].x, kpre[p].y, h0, l0);
                f16split2(kpre[p].z, kpre[p].w, h1, l1);
                *(uint2*)&nKh[rr * ASTR + kwc] = make_uint2(h0, h1);
                *(uint2*)&nKl[rr * ASTR + kwc] = make_uint2(l0, l1);
            }
            #pragma unroll
            for (int it = 0; it < 2; it++) {
                const int c = vc0 + 8 * it;
                const float* v0 = (const float*)&vpre[2 * it];
                const float* v1 = (const float*)&vpre[2 * it + 1];
                #pragma unroll
                for (int i = 0; i < 4; i++) {
                    uint32_t hw, lw;
                    f16split2(v0[i], v1[i], hw, lw);
                    nVh[(4 * c + i) * ASTR + vr] = hw;
                    nVl[(4 * c + i) * ASTR + vr] = lw;
                }
            }
            if (tid < 64) { nroleK[tid] = rpre; nkpmK[tid] = kppre; }
            __syncthreads();
        }
    }

    // ---- normalize + store ----
    const float i0 = (l0s > 0.f) ? (1.f / l0s) : 0.f;
    const float i1 = (l1s > 0.f) ? (1.f / l1s) : 0.f;
    #pragma unroll
    for (int n = 0; n < 8; n++) {
        float2 o0, o1;
        o0.x = O[n][0] * i0; o0.y = O[n][1] * i0;
        o1.x = O[n][2] * i1; o1.y = O[n][3] * i1;
        *(float2*)(g_A + base + (size_t)qg0 * DD + 8 * n + 2 * t4) = o0;
        *(float2*)(g_A + base + (size_t)qg1 * DD + 8 * n + 2 * t4) = o1;
    }
}

// ---------------------------------------------------------------------------
// Launch
// ---------------------------------------------------------------------------
extern "C" void kernel_launch(void* const* d_in, const int* in_sizes, int n_in,
                              void* d_out, int out_size)
{
    const float* x    = (const float*)d_in[0];
    const int*   role = (const int*)d_in[1];
    const int*   kpm_raw = (const int*)d_in[3];
    const float* Wq = (const float*)d_in[4];
    const float* bq = (const float*)d_in[5];
    const float* Wk = (const float*)d_in[6];
    const float* bk = (const float*)d_in[7];
    const float* Wv = (const float*)d_in[8];
    const float* bv = (const float*)d_in[9];
    const float* Wo = (const float*)d_in[10];
    const float* bo = (const float*)d_in[11];
    const float* delta = (const float*)d_in[12];

    float *qb, *kb, *vb, *ab;
    cudaGetSymbolAddress((void**)&qb, g_Q);
    cudaGetSymbolAddress((void**)&kb, g_K);
    cudaGetSymbolAddress((void**)&vb, g_V);
    cudaGetSymbolAddress((void**)&ab, g_A);

    cudaFuncSetAttribute(attn_f16,
                         cudaFuncAttributeMaxDynamicSharedMemorySize, ATT_SMEM);

    normalize_kpm<<<1, 256>>>(kpm_raw);

    // Fused Q/K/V projections: one balanced 768-CTA launch
    dim3 qkvgrid(1024 / 128, MROWS / 128, 3);   // (8, 32, 3)
    gemm_f16x3z<<<qkvgrid, 256>>>(x, Wq, bq, qb, Wk, bk, kb, Wv, bv, vb);

    dim3 agrid(LL / 128, HH, BB);               // (16, 16, 2)
    attn_f16<<<agrid, 256, ATT_SMEM>>>(role, delta);

    // Output projection: same kernel, gridDim.z = 1
    dim3 ogrid(1024 / 128, MROWS / 128, 1);     // (8, 32, 1)
    gemm_f16x3z<<<ogrid, 256>>>(ab, Wo, bo, (float*)d_out,
                                Wo, bo, (float*)d_out, Wo, bo, (float*)d_out);
}